// round 17
// baseline (speedup 1.0000x reference)
#include <cuda_runtime.h>

#define NT 128
#define PI_F 3.14159265358979323846f

struct __align__(16) CData {
    float2 W1[32];    // pair-interleaved: i -> p=i>>2,k=i&3 : (W1[2p][k], W1[2p+1][k])
    float  W2[512];   // plain row-major [32][16]
    float2 W3[256];   // pair-interleaved [8 pairs][32 k]
    float2 b1[8];
    float  b2[32];
    float2 b3[8];
    float2 K[30];     // Pauli coefficients, duplicated lanes
};

__constant__ CData cD;

// ---------- packed f32x2 primitives ----------
struct P2 { union { float2 f; unsigned long long u; }; };

__device__ __forceinline__ P2 mk2(float a, float b) { P2 p; p.f.x = a; p.f.y = b; return p; }
__device__ __forceinline__ P2 dup2(float a) { return mk2(a, a); }

__device__ __forceinline__ P2 fma2(P2 a, P2 b, P2 c) {
    P2 d;
    asm("fma.rn.f32x2 %0, %1, %2, %3;" : "=l"(d.u) : "l"(a.u), "l"(b.u), "l"(c.u));
    return d;
}
__device__ __forceinline__ P2 mul2(P2 a, P2 b) {
    P2 d;
    asm("mul.rn.f32x2 %0, %1, %2;" : "=l"(d.u) : "l"(a.u), "l"(b.u));
    return d;
}
__device__ __forceinline__ P2 relu2(P2 a) {
    P2 d; d.f.x = fmaxf(a.f.x, 0.f); d.f.y = fmaxf(a.f.y, 0.f); return d;
}

// ---------- prep kernel: rearrange weights + coefficients into cD's backing store ----------
__global__ void qae_prep(CData* __restrict__ dst,
                         const float* __restrict__ qw,
                         const float* __restrict__ W1, const float* __restrict__ b1,
                         const float* __restrict__ W2, const float* __restrict__ b2,
                         const float* __restrict__ W3, const float* __restrict__ b3)
{
    const int tid = threadIdx.x;   // 512 threads
    if (tid < 32) {
        int p = tid >> 2, k = tid & 3;
        dst->W1[tid] = make_float2(W1[(2 * p) * 4 + k], W1[(2 * p + 1) * 4 + k]);
    }
    if (tid < 512) dst->W2[tid] = W2[tid];
    if (tid < 256) {
        int p3 = tid >> 5, k3 = tid & 31;
        dst->W3[tid] = make_float2(W3[(2 * p3) * 32 + k3], W3[(2 * p3 + 1) * 32 + k3]);
    }
    if (tid < 8)  dst->b1[tid] = make_float2(b1[2 * tid], b1[2 * tid + 1]);
    if (tid < 32) dst->b2[tid] = b2[tid];
    if (tid < 8)  dst->b3[tid] = make_float2(b3[2 * tid], b3[2 * tid + 1]);
    if (tid == 0) {
        float c[4], s[4];
#pragma unroll
        for (int i = 0; i < 4; i++) __sincosf(qw[2 * i], &s[i], &c[i]);
        float kv[30];
        kv[0]  =  c[0];                    kv[1]  = -s[0];
        kv[2]  =  c[0] * c[1];             kv[3]  = -c[0] * s[1];
        kv[4]  =  s[0] * c[1];             kv[5]  =  s[0] * s[1];
        kv[6]  =  c[0] * c[1] * c[2];      kv[7]  = -c[0] * c[1] * s[2];
        kv[8]  =  c[0] * s[1] * c[2];      kv[9]  =  c[0] * s[1] * s[2];
        kv[10] = -s[0] * c[1] * c[2];      kv[11] = -s[0] * c[1] * s[2];
        kv[12] = -s[0] * s[1] * c[2];      kv[13] = -s[0] * s[1] * s[2];
        kv[14] =  c[0] * c[1] * c[2] * c[3];
        kv[15] =  s[0] * c[1] * c[2] * c[3];
        kv[16] = -c[0] * s[1] * c[2] * c[3];
        kv[17] =  c[0] * c[1] * s[2] * c[3];
        kv[18] = -c[0] * c[1] * c[2] * s[3];
        kv[19] =  s[0] * s[1] * c[2] * c[3];
        kv[20] = -s[0] * c[1] * s[2] * c[3];
        kv[21] =  s[0] * c[1] * c[2] * s[3];
        kv[22] = -c[0] * s[1] * s[2] * c[3];
        kv[23] = -c[0] * s[1] * c[2] * s[3];
        kv[24] =  c[0] * c[1] * s[2] * s[3];
        kv[25] =  s[0] * s[1] * s[2] * c[3];
        kv[26] =  s[0] * s[1] * c[2] * s[3];
        kv[27] =  s[0] * c[1] * s[2] * s[3];
        kv[28] = -c[0] * s[1] * s[2] * s[3];
        kv[29] =  s[0] * s[1] * s[2] * s[3];
#pragma unroll
        for (int i = 0; i < 30; i++) dst->K[i] = make_float2(kv[i], kv[i]);
    }
}

// Bloch-sphere / Pauli-string collapsed quantum encoder for one lane-packed row pair.
__device__ __forceinline__ void compute_zv(const float xsA[8], const float xsB[8], P2 zv[4])
{
    P2 X[4], Y[4], Z[4];
#pragma unroll
    for (int i = 0; i < 4; i++) {
        float saA, caA, sbA, cbA, saB, caB, sbB, cbB;
        __sincosf(xsA[i]     * PI_F, &saA, &caA);
        __sincosf(xsA[i + 4] * PI_F, &sbA, &cbA);
        __sincosf(xsB[i]     * PI_F, &saB, &caB);
        __sincosf(xsB[i + 4] * PI_F, &sbB, &cbB);
        P2 sa = mk2(saA, saB), sb = mk2(sbA, sbB), cb = mk2(cbA, cbB);
        X[i] = mul2(sa, cb);
        Y[i] = mul2(sa, sb);
        Z[i] = mk2(caA, caB);
    }

    P2 A  = mul2(X[0], X[1]);
    P2 B  = mul2(Y[0], Y[1]);
    P2 F  = mul2(X[1], X[2]);
    P2 H  = mul2(X[0], X[2]);
    P2 D  = mul2(X[2], X[3]);
    P2 E  = mul2(Y[2], Y[3]);
    P2 G  = mul2(Y[1], Y[2]);
    P2 ZF = mul2(Z[0], F);
    P2 Z0Z2 = mul2(Z[0], Z[2]);
    P2 YZ   = mul2(Y[0], Z[1]);
    P2 YZY  = mul2(YZ, Y[2]);

#define KLD(n) ({ P2 _k; _k.f = cD.K[n]; _k; })

    P2 z0 = mul2(KLD(0), Z[0]);
    z0 = fma2(KLD(1), A, z0);

    P2 z1 = mul2(KLD(2), Z[1]);
    z1 = fma2(KLD(3), ZF, z1);
    z1 = fma2(KLD(4), B, z1);
    z1 = fma2(KLD(5), H, z1);

    P2 Z1D   = mul2(Z[1], D);
    P2 X1X3  = mul2(X[1], X[3]);
    P2 ZX1X3 = mul2(Z[0], X1X3);
    P2 AZ2   = mul2(A, Z[2]);
    P2 BD    = mul2(B, D);
    P2 X0X3  = mul2(X[0], X[3]);
    P2 z2 = mul2(KLD(6), Z0Z2);
    z2 = fma2(KLD(7),  Z1D,   z2);
    z2 = fma2(KLD(8),  G,     z2);
    z2 = fma2(KLD(9),  ZX1X3, z2);
    z2 = fma2(KLD(10), AZ2,   z2);
    z2 = fma2(KLD(11), BD,    z2);
    z2 = fma2(KLD(12), YZY,   z2);
    z2 = fma2(KLD(13), X0X3,  z2);

    P2 Z1Z3 = mul2(Z[1], Z[3]);
    P2 BZ3  = mul2(B, Z[3]);
    P2 ZF3  = mul2(ZF, Z[3]);
    P2 Z0E  = mul2(Z[0], E);
    P2 ZZX  = mul2(Z0Z2, X[3]);
    P2 HZ3  = mul2(H, Z[3]);
    P2 AE   = mul2(A, E);
    P2 AZX  = mul2(AZ2, X[3]);
    P2 Y1Z2 = mul2(Y[1], Z[2]);
    P2 YZ2Y3 = mul2(Y1Z2, Y[3]);
    P2 GX3  = mul2(G, X[3]);
    P2 Z1X2 = mul2(Z[1], X[2]);
    P2 YZZ  = mul2(YZ, Z[2]);
    P2 YZZY = mul2(YZZ, Y[3]);
    P2 YZYX = mul2(YZY, X[3]);
    P2 BX2  = mul2(B, X[2]);
    P2 Z0X1 = mul2(Z[0], X[1]);
    P2 z3 = mul2(KLD(14), Z1Z3);
    z3 = fma2(KLD(15), BZ3,   z3);
    z3 = fma2(KLD(16), ZF3,   z3);
    z3 = fma2(KLD(17), Z0E,   z3);
    z3 = fma2(KLD(18), ZZX,   z3);
    z3 = fma2(KLD(19), HZ3,   z3);
    z3 = fma2(KLD(20), AE,    z3);
    z3 = fma2(KLD(21), AZX,   z3);
    z3 = fma2(KLD(22), YZ2Y3, z3);
    z3 = fma2(KLD(23), GX3,   z3);
    z3 = fma2(KLD(24), Z1X2,  z3);
    z3 = fma2(KLD(25), YZZY,  z3);
    z3 = fma2(KLD(26), YZYX,  z3);
    z3 = fma2(KLD(27), BX2,   z3);
    z3 = fma2(KLD(28), Z0X1,  z3);
    z3 = fma2(KLD(29), X[0],  z3);

    zv[0] = z0; zv[1] = z1; zv[2] = z2; zv[3] = z3;
}

__global__ void __launch_bounds__(NT)
qae17_kernel(const float* __restrict__ x, float* __restrict__ out, int nrows)
{
    const int tid = threadIdx.x;
    // 4 rows per thread: pair P = (base, base+NT), pair Q = (base+2NT, base+3NT)
    const int base = blockIdx.x * (NT * 4) + tid;
    if (base >= nrows) return;
    int r[4];
    bool has[4];
#pragma unroll
    for (int s = 0; s < 4; s++) {
        int rr = base + s * NT;
        has[s] = (rr < nrows);
        r[s] = has[s] ? rr : base;
    }

    // ---- load features (front-batched) ----
    float4 f0[4], f1[4];
#pragma unroll
    for (int s = 0; s < 4; s++) {
        const float4* xp = reinterpret_cast<const float4*>(x + (size_t)r[s] * 16);
        f0[s] = xp[0]; f1[s] = xp[1];
    }

    // ---- quantum encoder, two lane-packed pairs ----
    P2 zvP[4], zvQ[4];
    {
        float xsA[8] = {f0[0].x, f0[0].y, f0[0].z, f0[0].w, f1[0].x, f1[0].y, f1[0].z, f1[0].w};
        float xsB[8] = {f0[1].x, f0[1].y, f0[1].z, f0[1].w, f1[1].x, f1[1].y, f1[1].z, f1[1].w};
        compute_zv(xsA, xsB, zvP);
    }
    {
        float xsA[8] = {f0[2].x, f0[2].y, f0[2].z, f0[2].w, f1[2].x, f1[2].y, f1[2].z, f1[2].w};
        float xsB[8] = {f0[3].x, f0[3].y, f0[3].z, f0[3].w, f1[3].x, f1[3].y, f1[3].z, f1[3].w};
        compute_zv(xsA, xsB, zvQ);
    }

    // ---- Layer 1: 4 -> 16 for all four rows; each weight load feeds 4 rows ----
    P2 zdPA[4], zdPB[4], zdQA[4], zdQB[4];
#pragma unroll
    for (int k = 0; k < 4; k++) {
        zdPA[k] = dup2(zvP[k].f.x); zdPB[k] = dup2(zvP[k].f.y);
        zdQA[k] = dup2(zvQ[k].f.x); zdQB[k] = dup2(zvQ[k].f.y);
    }

    P2 h1PA[8], h1PB[8], h1QA[8], h1QB[8];
#pragma unroll
    for (int pp = 0; pp < 8; pp++) {
        const float4* wp = reinterpret_cast<const float4*>(cD.W1 + pp * 4);
        float4 w0 = wp[0], w1 = wp[1];
        P2 wk0 = mk2(w0.x, w0.y), wk1 = mk2(w0.z, w0.w);
        P2 wk2 = mk2(w1.x, w1.y), wk3 = mk2(w1.z, w1.w);
        P2 bias; bias.f = cD.b1[pp];
        P2 aPA = bias, aPB = bias, aQA = bias, aQB = bias;
        aPA = fma2(wk0, zdPA[0], aPA); aPB = fma2(wk0, zdPB[0], aPB);
        aQA = fma2(wk0, zdQA[0], aQA); aQB = fma2(wk0, zdQB[0], aQB);
        aPA = fma2(wk1, zdPA[1], aPA); aPB = fma2(wk1, zdPB[1], aPB);
        aQA = fma2(wk1, zdQA[1], aQA); aQB = fma2(wk1, zdQB[1], aQB);
        aPA = fma2(wk2, zdPA[2], aPA); aPB = fma2(wk2, zdPB[2], aPB);
        aQA = fma2(wk2, zdQA[2], aQA); aQB = fma2(wk2, zdQB[2], aQB);
        aPA = fma2(wk3, zdPA[3], aPA); aPB = fma2(wk3, zdPB[3], aPB);
        aQA = fma2(wk3, zdQA[3], aQA); aQB = fma2(wk3, zdQB[3], aQB);
        h1PA[pp] = relu2(aPA); h1PB[pp] = relu2(aPB);
        h1QA[pp] = relu2(aQA); h1QB[pp] = relu2(aQB);
    }

    // ---- Fused Layers 2+3 for all four rows; weights loaded once per ch ----
    P2 oPA[8], oPB[8], oQA[8], oQB[8];
#pragma unroll
    for (int qq = 0; qq < 8; qq++) {
        P2 bias; bias.f = cD.b3[qq];
        oPA[qq] = bias; oPB[qq] = bias; oQA[qq] = bias; oQB[qq] = bias;
    }

#pragma unroll
    for (int ch = 0; ch < 16; ch++) {
        const float4* w2r0 = reinterpret_cast<const float4*>(cD.W2 + (2 * ch) * 16);
        const float4* w2r1 = reinterpret_cast<const float4*>(cD.W2 + (2 * ch + 1) * 16);
        P2 b0 = mk2(cD.b2[2 * ch], 0.f);
        P2 b1v = mk2(cD.b2[2 * ch + 1], 0.f);
        P2 aPA0 = b0, aPA1 = b1v, aPB0 = b0, aPB1 = b1v;
        P2 aQA0 = b0, aQA1 = b1v, aQB0 = b0, aQB1 = b1v;
#pragma unroll
        for (int j4 = 0; j4 < 4; j4++) {
            float4 w0 = w2r0[j4];
            float4 w1 = w2r1[j4];
            P2 w0a = mk2(w0.x, w0.y), w0b = mk2(w0.z, w0.w);
            P2 w1a = mk2(w1.x, w1.y), w1b = mk2(w1.z, w1.w);
            P2 hPA0 = h1PA[2 * j4], hPA1 = h1PA[2 * j4 + 1];
            P2 hPB0 = h1PB[2 * j4], hPB1 = h1PB[2 * j4 + 1];
            P2 hQA0 = h1QA[2 * j4], hQA1 = h1QA[2 * j4 + 1];
            P2 hQB0 = h1QB[2 * j4], hQB1 = h1QB[2 * j4 + 1];
            aPA0 = fma2(w0a, hPA0, aPA0); aPA0 = fma2(w0b, hPA1, aPA0);
            aPA1 = fma2(w1a, hPA0, aPA1); aPA1 = fma2(w1b, hPA1, aPA1);
            aPB0 = fma2(w0a, hPB0, aPB0); aPB0 = fma2(w0b, hPB1, aPB0);
            aPB1 = fma2(w1a, hPB0, aPB1); aPB1 = fma2(w1b, hPB1, aPB1);
            aQA0 = fma2(w0a, hQA0, aQA0); aQA0 = fma2(w0b, hQA1, aQA0);
            aQA1 = fma2(w1a, hQA0, aQA1); aQA1 = fma2(w1b, hQA1, aQA1);
            aQB0 = fma2(w0a, hQB0, aQB0); aQB0 = fma2(w0b, hQB1, aQB0);
            aQB1 = fma2(w1a, hQB0, aQB1); aQB1 = fma2(w1b, hQB1, aQB1);
        }
        P2 hdPA0 = dup2(fmaxf(aPA0.f.x + aPA0.f.y, 0.f));
        P2 hdPA1 = dup2(fmaxf(aPA1.f.x + aPA1.f.y, 0.f));
        P2 hdPB0 = dup2(fmaxf(aPB0.f.x + aPB0.f.y, 0.f));
        P2 hdPB1 = dup2(fmaxf(aPB1.f.x + aPB1.f.y, 0.f));
        P2 hdQA0 = dup2(fmaxf(aQA0.f.x + aQA0.f.y, 0.f));
        P2 hdQA1 = dup2(fmaxf(aQA1.f.x + aQA1.f.y, 0.f));
        P2 hdQB0 = dup2(fmaxf(aQB0.f.x + aQB0.f.y, 0.f));
        P2 hdQB1 = dup2(fmaxf(aQB1.f.x + aQB1.f.y, 0.f));

#pragma unroll
        for (int qq = 0; qq < 8; qq++) {
            const float4* w3p = reinterpret_cast<const float4*>(cD.W3 + qq * 32 + ch * 2);
            float4 w = w3p[0];
            P2 wa = mk2(w.x, w.y), wb = mk2(w.z, w.w);
            oPA[qq] = fma2(wa, hdPA0, oPA[qq]); oPA[qq] = fma2(wb, hdPA1, oPA[qq]);
            oPB[qq] = fma2(wa, hdPB0, oPB[qq]); oPB[qq] = fma2(wb, hdPB1, oPB[qq]);
            oQA[qq] = fma2(wa, hdQA0, oQA[qq]); oQA[qq] = fma2(wb, hdQA1, oQA[qq]);
            oQB[qq] = fma2(wa, hdQB0, oQB[qq]); oQB[qq] = fma2(wb, hdQB1, oQB[qq]);
        }
    }

    // ---- stores ----
    {
        float4* op = reinterpret_cast<float4*>(out + (size_t)r[0] * 16);
#pragma unroll
        for (int q = 0; q < 4; q++)
            op[q] = make_float4(oPA[2 * q].f.x, oPA[2 * q].f.y, oPA[2 * q + 1].f.x, oPA[2 * q + 1].f.y);
    }
    if (has[1]) {
        float4* op = reinterpret_cast<float4*>(out + (size_t)(base + NT) * 16);
#pragma unroll
        for (int q = 0; q < 4; q++)
            op[q] = make_float4(oPB[2 * q].f.x, oPB[2 * q].f.y, oPB[2 * q + 1].f.x, oPB[2 * q + 1].f.y);
    }
    if (has[2]) {
        float4* op = reinterpret_cast<float4*>(out + (size_t)(base + 2 * NT) * 16);
#pragma unroll
        for (int q = 0; q < 4; q++)
            op[q] = make_float4(oQA[2 * q].f.x, oQA[2 * q].f.y, oQA[2 * q + 1].f.x, oQA[2 * q + 1].f.y);
    }
    if (has[3]) {
        float4* op = reinterpret_cast<float4*>(out + (size_t)(base + 3 * NT) * 16);
#pragma unroll
        for (int q = 0; q < 4; q++)
            op[q] = make_float4(oQB[2 * q].f.x, oQB[2 * q].f.y, oQB[2 * q + 1].f.x, oQB[2 * q + 1].f.y);
    }
}

extern "C" void kernel_launch(void* const* d_in, const int* in_sizes, int n_in,
                              void* d_out, int out_size) {
    const float* x  = (const float*)d_in[0];
    const float* qw = (const float*)d_in[1];
    const float* W1 = (const float*)d_in[2];
    const float* b1 = (const float*)d_in[3];
    const float* W2 = (const float*)d_in[4];
    const float* b2 = (const float*)d_in[5];
    const float* W3 = (const float*)d_in[6];
    const float* b3 = (const float*)d_in[7];
    float* out = (float*)d_out;

    int nrows = in_sizes[0] / 16;

    void* cptr = nullptr;
    cudaGetSymbolAddress(&cptr, cD);   // pure query; capture-safe
    qae_prep<<<1, 512>>>((CData*)cptr, qw, W1, b1, W2, b2, W3, b3);

    int grid = (nrows + NT * 4 - 1) / (NT * 4);
    qae17_kernel<<<grid, NT>>>(x, out, nrows);
}